// round 13
// baseline (speedup 1.0000x reference)
#include <cuda_runtime.h>
#include <cstdint>

// ---------------------------------------------------------------------------
// UniformAssigner — flat chassis, 3 launches, ANC=1 for full occupancy.
//  k_main  : 1 anchor/thread (grid 782 -> ~42 warps/SM); branch-free sweep
//            builds 4x u32 candidate masks via m = m*2 + p. Epilogue: exact
//            reference IoU on ~0.6 bits/thread, ign flag, lock-free per-gt
//            top-4 (s3-filtered atomicMax cascade).
//  k_scatter: <=512 entries -> atomicMax gt_id onto assigned[anchor].
//  k_final : labels + bboxes (out[0:N]=labels, out[N:5N]=bboxes); block 0
//            re-zeroes g_topk for the next graph replay (zero-init covers
//            the first execution; scatter precedes final, so no race).
// ---------------------------------------------------------------------------

#define MAXM 128
#define MAXN (1u << 20)
typedef unsigned long long ull;

__device__ ull g_topk[MAXM * 4];      // packed (iou_bits<<32|idx), 0 = empty
__device__ int g_assigned[MAXN];      // baseline 0/-1, then gt ids

// lock-free top-4 insert; slots monotone non-decreasing, pairwise sorted.
__device__ __forceinline__ void topk_insert(int g, float iou, unsigned idx) {
    ull key = ((ull)__float_as_uint(iou) << 32) | idx;
    ull* slots = &g_topk[g * 4];
    // stale slot[3] read can only be <= current -> skip on key<=read is safe.
    ull s3;
    asm volatile("ld.global.cg.u64 %0, [%1];" : "=l"(s3) : "l"(slots + 3));
    if (key > s3) {
#pragma unroll
        for (int s = 0; s < 4; s++) {
            ull prev = atomicMax(&slots[s], key);
            if (prev == 0ULL) break;        // landed in an empty slot
            key = prev < key ? prev : key;  // push displaced smaller key down
        }
    }
}

// ---------------------------------------------------------------- main ------
__global__ void __launch_bounds__(256)
k_main(const float4* __restrict__ anchors, const float4* __restrict__ gts,
       int N, int M) {
    __shared__ float4 sbox[MAXM];
    __shared__ float  sarea[MAXM];   // exact gt area (epilogue / union)
    __shared__ float  sthr[MAXM];    // 0.12 * gt area (conservative gate)
    for (int g = threadIdx.x; g < M; g += blockDim.x) {
        float4 b  = gts[g];
        float  ar = (b.z - b.x) * (b.w - b.y);
        sbox[g]  = b;
        sarea[g] = ar;
        sthr[g]  = 0.12f * ar;
    }
    __syncthreads();

    const int i = blockIdx.x * blockDim.x + threadIdx.x;
    if (i >= N) return;

    const float4 a     = anchors[i];
    const float  areaA = (a.z - a.x) * (a.w - a.y);
    const float  tA    = 0.12f * areaA;

    // ---- branch-free sweep: 4x u32 masks, IMAD accumulation --------------
    // gate: max(iw,0)*ih >= tA + thr.  thr >= 0.12*128 > 0 and a single
    // clamp kills the (-)*(-) false positive:
    //   ih<0       -> product <= 0 < thr
    //   iw<0,ih>0  -> 0*ih    =  0 < thr
    // true candidates (iou>=0.15 => both extents>0) are never dropped.
    unsigned msk[4];
#pragma unroll
    for (int w = 0; w < 4; w++) {
        int base = w * 32;
        unsigned m = 0;
        if (base < M) {
            int lim = M - base;
            if (lim > 32) lim = 32;
#pragma unroll 4
            for (int j = 0; j < lim; j++) {
                float4 b   = sbox[base + j];
                float  thr = sthr[base + j];
                float iw = fminf(a.z, b.z) - fmaxf(a.x, b.x);
                float ih = fminf(a.w, b.w) - fmaxf(a.y, b.y);
                float in = fmaxf(iw, 0.0f) * ih;
                m = m * 2u + (unsigned)(in >= tA + thr);   // IMAD
            }
            if (lim < 32) {              // normalize: bit(31-j) <-> g=base+j
                m <<= (32 - lim);
            }
        }
        msk[w] = m;
    }

    // ---- epilogue: exact reference math on rare candidates ---------------
    int ign = 0;
#pragma unroll
    for (int w = 0; w < 4; w++) {
        int base = w * 32;
        unsigned m = msk[w];
        while (m) {
            int j = __clz(m);
            m &= ~(0x80000000u >> j);
            int g = base + j;
            float4 b = sbox[g];
            float iw    = fminf(a.z, b.z) - fmaxf(a.x, b.x);
            float ih    = fminf(a.w, b.w) - fmaxf(a.y, b.y);
            float inter = fmaxf(iw, 0.0f) * fmaxf(ih, 0.0f);
            float uni   = (areaA + sarea[g]) - inter;
            float iou   = inter / fmaxf(uni, 1e-7f);   // exact ref expression
            ign |= (iou >= 0.7f);
            if (iou >= 0.15f) topk_insert(g, iou, (unsigned)i);
        }
    }

    g_assigned[i] = ign ? -1 : 0;
}

// ------------------------------------------------------------- scatter ------
__global__ void k_scatter(int M) {
    int i = blockIdx.x * blockDim.x + threadIdx.x;
    if (i >= M * 4) return;
    ull key = g_topk[i];
    if (key == 0ULL) return;
    float iou = __uint_as_float((unsigned)(key >> 32));
    if (iou >= 0.15f) {
        int idx = (int)(key & 0xffffffffULL);
        atomicMax(&g_assigned[idx], i / 4 + 1);
    }
}

// ------------------------------------------------------------ finalize ------
__global__ void __launch_bounds__(256)
k_final(const float4* __restrict__ gts, const int* __restrict__ labels,
        float* __restrict__ out, int N) {
    // block 0: re-zero g_topk for the next graph replay (scatter already ran;
    // nothing in this kernel reads g_topk).
    if (blockIdx.x == 0) {
#pragma unroll
        for (int k = 0; k < 2; k++) g_topk[threadIdx.x + k * 256] = 0ULL;
    }

    const int i = blockIdx.x * blockDim.x + threadIdx.x;
    if (i >= N) return;
    int a = g_assigned[i];
    float  lab;
    float4 bb;
    if (a > 0) {
        lab = (float)labels[a - 1];
        bb  = gts[a - 1];
    } else {
        lab = (a == 0) ? 0.0f : -1.0f;
        bb  = make_float4(-1.0f, -1.0f, -1.0f, -1.0f);
    }
    out[i] = lab;
    if ((N & 3) == 0) {
        reinterpret_cast<float4*>(out + N)[i] = bb;   // out+N is 16B-aligned
    } else {
        float* p = out + N + 4 * i;
        p[0] = bb.x; p[1] = bb.y; p[2] = bb.z; p[3] = bb.w;
    }
}

// --------------------------------------------------------------------------
extern "C" void kernel_launch(void* const* d_in, const int* in_sizes, int n_in,
                              void* d_out, int out_size) {
    const float4* anchors = (const float4*)d_in[0];
    const float4* gts     = (const float4*)d_in[1];
    const int*    labels  = (const int*)d_in[2];
    int N = in_sizes[0] / 4;
    int M = in_sizes[1] / 4;
    float* out = (float*)d_out;

    k_main<<<(N + 255) / 256, 256>>>(anchors, gts, N, M);   // 782 blocks
    k_scatter<<<(M * 4 + 255) / 256, 256>>>(M);
    k_final<<<(N + 255) / 256, 256>>>(gts, labels, out, N);
}